// round 8
// baseline (speedup 1.0000x reference)
#include <cuda_runtime.h>
#include <math.h>

#define Bc 256
#define Vc 4096
#define Kc 64
#define MINIf 1e-6f

#define VK (Vc*Kc)             /* 262144 */
#define BK (Bc*Kc)             /* 16384  */
#define OUT_TN 0
#define OUT_TM VK
#define OUT_QZ (VK+BK)
#define OUT_NN (VK+BK+1)
#define OUT_NM (VK+BK+1+VK)

// device scratch
__device__ float g_theta[BK];
__device__ float g_thetaL[BK];
__device__ float g_phi[VK];
__device__ float g_phiL[VK];
__device__ float g_Nacc[VK];
__device__ float g_Macc[BK];
__device__ float g_denom[Kc];        // zero-init at load; re-zeroed by k2's last block
__device__ unsigned g_k2cnt;         // wrap counter, self-resets
__device__ float g_rho;
__device__ float g_ratio;
__device__ int   g_idxstride;

// ---- PDL (programmatic dependent launch) ------------------------------------
#define GDC_LAUNCH() asm volatile("griddepcontrol.launch_dependents;" ::: "memory")
#define GDC_WAIT()   asm volatile("griddepcontrol.wait;" ::: "memory")

// ---- packed f32x2 helpers (Blackwell FFMA2) --------------------------------
__device__ __forceinline__ void pfma(unsigned long long& acc,
                                     unsigned long long a, unsigned long long b) {
    asm("fma.rn.f32x2 %0, %1, %2, %0;" : "+l"(acc) : "l"(a), "l"(b));
}
__device__ __forceinline__ float psum(unsigned long long v) {
    return __uint_as_float((unsigned)v) + __uint_as_float((unsigned)(v >> 32));
}
__device__ __forceinline__ unsigned long long fpack2(float lo, float hi) {
    unsigned long long r;
    asm("mov.b64 %0, {%1, %2};" : "=l"(r) : "f"(lo), "f"(hi));
    return r;
}
__device__ __forceinline__ void punpack(unsigned long long v, float& lo, float& hi) {
    lo = __uint_as_float((unsigned)v);
    hi = __uint_as_float((unsigned)(v >> 32));
}

// ---------------------------------------------------------------------------
// K1: per-topic denominator into g_denom (zeroed by previous call's k2),
// plus scalars / index probe / entropy-slot zero.
__global__ void __launch_bounds__(256) k1_denom(
        const float* __restrict__ beta,
        const float* __restrict__ expn,
        const int* __restrict__ iterp,
        const int* __restrict__ cmp,
        const int* __restrict__ bcp,
        const unsigned int* __restrict__ idxw,
        float* __restrict__ out) {
    GDC_LAUNCH();
    if (blockIdx.x < 128) {
        __shared__ float red[16][68];
        int t = threadIdx.x;
        int cq = t & 15, r = t >> 4;
        int v0 = blockIdx.x * 32;
        float4 b0 = ((const float4*)beta)[(v0 + r     ) * 16 + cq];
        float4 b1 = ((const float4*)beta)[(v0 + r + 16) * 16 + cq];
        float4 e0 = ((const float4*)expn)[(v0 + r     ) * 16 + cq];
        float4 e1 = ((const float4*)expn)[(v0 + r + 16) * 16 + cq];
        float4 a;
        a.x = (b0.x + e0.x) + (b1.x + e1.x);
        a.y = (b0.y + e0.y) + (b1.y + e1.y);
        a.z = (b0.z + e0.z) + (b1.z + e1.z);
        a.w = (b0.w + e0.w) + (b1.w + e1.w);
        *(float4*)&red[r][cq * 4] = a;
        __syncthreads();
        if (t < 64) {
            float s = 0.f;
            #pragma unroll
            for (int r2 = 0; r2 < 16; ++r2) s += red[r2][t];
            atomicAdd(&g_denom[t], s);
        }
    } else if (threadIdx.x == 0) {
        g_rho   = 1.f / powf((float)(iterp[0] + 5), 0.9f);
        g_ratio = (float)cmp[0] / (float)bcp[0];
        // int64-vs-int32 probe: if int64, odd 32-bit words (high halves) are 0.
        bool allz = true;
        for (int i = 1; i < Bc; i += 2)
            if (idxw[i] != 0u) { allz = false; break; }
        g_idxstride = allz ? 2 : 1;
        out[OUT_QZ] = 0.f;
    }
}

// ---------------------------------------------------------------------------
// K2: phi/phiL/theta/thetaL + accumulator zeroing. PDL: input loads in the
// preamble, wait before consuming k1 products. Last block re-zeroes g_denom.
__global__ void __launch_bounds__(256) k2_prep(
        const float* __restrict__ beta,
        const float* __restrict__ expn,
        const float* __restrict__ alpha,
        const float* __restrict__ pi,
        const float* __restrict__ expm,
        const unsigned int* __restrict__ idxw) {
    GDC_LAUNCH();
    int i4 = blockIdx.x * 256 + threadIdx.x;
    const float4 z4 = make_float4(0.f, 0.f, 0.f, 0.f);
    if (i4 < VK / 4) {
        int k4 = i4 & 15;
        float4 b = ((const float4*)beta)[i4];    // inputs: safe pre-wait
        float4 e = ((const float4*)expn)[i4];
        GDC_WAIT();
        float4 dn = ((const float4*)g_denom)[k4];
        float4 p;
        p.x = __fdividef(b.x + e.x, dn.x);
        p.y = __fdividef(b.y + e.y, dn.y);
        p.z = __fdividef(b.z + e.z, dn.z);
        p.w = __fdividef(b.w + e.w, dn.w);
        float4 pl;
        pl.x = p.x * __logf(p.x);
        pl.y = p.y * __logf(p.y);
        pl.z = p.z * __logf(p.z);
        pl.w = p.w * __logf(p.w);
        ((float4*)g_phi )[i4] = p;
        ((float4*)g_phiL)[i4] = pl;
        ((float4*)g_Nacc)[i4] = z4;
    } else {
        GDC_WAIT();                               // needs g_idxstride from k1
        int j4 = i4 - VK / 4;           // 0..4095
        int b = j4 >> 4, k4 = j4 & 15;
        int d = (int)idxw[b * g_idxstride];
        float4 al = ((const float4*)alpha)[k4];
        float4 pp = ((const float4*)pi  )[d * 16 + k4];
        float4 em = ((const float4*)expm)[d * 16 + k4];
        float4 th;
        th.x = fmaf(al.x, pp.x, em.x);
        th.y = fmaf(al.y, pp.y, em.y);
        th.z = fmaf(al.z, pp.z, em.z);
        th.w = fmaf(al.w, pp.w, em.w);
        float4 tl;
        tl.x = th.x * __logf(th.x);
        tl.y = th.y * __logf(th.y);
        tl.z = th.z * __logf(th.z);
        tl.w = th.w * __logf(th.w);
        ((float4*)g_theta )[j4] = th;
        ((float4*)g_thetaL)[j4] = tl;
        ((float4*)g_Macc  )[j4] = z4;
    }
    // last-finishing block re-zeroes g_denom for the next invocation.
    // Safe: every phi thread's denom load fed an FDIV before __syncthreads(),
    // so all denom reads completed before this block's counter arrival.
    __syncthreads();
    __shared__ int s_last;
    if (threadIdx.x == 0)
        s_last = (atomicInc(&g_k2cnt, 271u) == 271u);   // wraps 271 -> 0
    __syncthreads();
    if (s_last && threadIdx.x < 16)
        ((float4*)g_denom)[threadIdx.x] = z4;
}

// ---------------------------------------------------------------------------
// K3 fused: per block 64b x 64v tile. PDL: bow loads in the preamble.
__global__ void __launch_bounds__(256, 2)
k3_fused(const int* __restrict__ bow, float* __restrict__ out) {
    extern __shared__ float sm3[];
    float (*th)[68]  = (float(*)[68])(sm3);
    float (*thL)[68] = (float(*)[68])(sm3 + 64 * 68);   // becomes Wt in phase 2
    float (*ph)[68]  = (float(*)[68])(sm3 + 128 * 68);
    float (*phL)[68] = (float(*)[68])(sm3 + 192 * 68);
    float (*Wt)[68]  = thL;

    GDC_LAUNCH();

    int t = threadIdx.x;
    int v0 = blockIdx.x * 64;
    int b0 = blockIdx.y * 64;

    int tv = t & 15;       // v_local = tv + 16*vi
    int tb = t >> 4;       // b_local = tb + 16*bi

    // preamble: scattered bow loads (pure input) overlap k2's tail via PDL
    int cnt[4][4];
    #pragma unroll
    for (int bi = 0; bi < 4; ++bi)
        #pragma unroll
        for (int vi = 0; vi < 4; ++vi)
            cnt[bi][vi] = bow[(b0 + tb + 16 * bi) * Vc + v0 + tv + 16 * vi];

    GDC_WAIT();

    for (int i = t; i < 64 * 16; i += 256) {
        int r = i >> 4, cq = i & 15;
        *(float4*)&th [r][cq * 4] = ((const float4*)g_theta )[(b0 + r) * 16 + cq];
        *(float4*)&thL[r][cq * 4] = ((const float4*)g_thetaL)[(b0 + r) * 16 + cq];
        *(float4*)&ph [r][cq * 4] = ((const float4*)g_phi   )[(v0 + r) * 16 + cq];
        *(float4*)&phL[r][cq * 4] = ((const float4*)g_phiL  )[(v0 + r) * 16 + cq];
    }
    __syncthreads();

    unsigned long long S2[4][4], A2[4][4];
    #pragma unroll
    for (int bi = 0; bi < 4; ++bi)
        #pragma unroll
        for (int vi = 0; vi < 4; ++vi) { S2[bi][vi] = 0ull; A2[bi][vi] = 0ull; }

    #pragma unroll 4
    for (int kq = 0; kq < 16; ++kq) {
        ulonglong2 P[4], Q[4];
        #pragma unroll
        for (int vi = 0; vi < 4; ++vi) {
            P[vi] = *(const ulonglong2*)&ph [tv + 16 * vi][kq * 4];
            Q[vi] = *(const ulonglong2*)&phL[tv + 16 * vi][kq * 4];
        }
        #pragma unroll
        for (int bi = 0; bi < 4; ++bi) {
            ulonglong2 T = *(const ulonglong2*)&th [tb + 16 * bi][kq * 4];
            ulonglong2 L = *(const ulonglong2*)&thL[tb + 16 * bi][kq * 4];
            #pragma unroll
            for (int vi = 0; vi < 4; ++vi) {
                pfma(S2[bi][vi], T.x, P[vi].x);
                pfma(S2[bi][vi], T.y, P[vi].y);
                pfma(A2[bi][vi], L.x, P[vi].x);
                pfma(A2[bi][vi], L.y, P[vi].y);
                pfma(A2[bi][vi], T.x, Q[vi].x);
                pfma(A2[bi][vi], T.y, Q[vi].y);
            }
        }
    }

    // epilogue of phase 1: w, entropy (MUFU rcp/log — hidden under FMA issue)
    float wv[4][4];
    float ent = 0.f;
    #pragma unroll
    for (int bi = 0; bi < 4; ++bi) {
        #pragma unroll
        for (int vi = 0; vi < 4; ++vi) {
            float S = psum(S2[bi][vi]);
            float A = psum(A2[bi][vi]);
            float sp = S + MINIf;
            float r  = __fdividef(1.f, sp);
            int c = cnt[bi][vi];
            wv[bi][vi] = (float)c * r;
            if (c > 0)
                ent += (A - S * __logf(sp)) * r;
        }
    }

    // block entropy reduction
    #pragma unroll
    for (int o = 16; o; o >>= 1)
        ent += __shfl_xor_sync(0xFFFFFFFFu, ent, o);
    __shared__ float ered[8];
    if ((t & 31) == 0) ered[t >> 5] = ent;

    __syncthreads();   // all thL reads done; ered visible
    if (t == 0) {
        float s = 0.f;
        #pragma unroll
        for (int w = 0; w < 8; ++w) s += ered[w];
        atomicAdd(&out[OUT_QZ], s);
    }

    // stage W into smem (overwrites thL)
    #pragma unroll
    for (int bi = 0; bi < 4; ++bi)
        #pragma unroll
        for (int vi = 0; vi < 4; ++vi)
            Wt[tb + 16 * bi][tv + 16 * vi] = wv[bi][vi];
    __syncthreads();

    // ---- phase 2 ----
    int kq2 = t & 15;            // k = kq2*4 .. +3
    int tr  = t >> 4;            // row group: tr + 16*j

    // 2a: Macc[b, k] += sum_c Wt[b_local][c] * ph[c][k]
    {
        unsigned long long acc[4][2];
        #pragma unroll
        for (int j = 0; j < 4; ++j) { acc[j][0] = 0ull; acc[j][1] = 0ull; }
        #pragma unroll 8
        for (int c = 0; c < 64; ++c) {
            ulonglong2 p2 = *(const ulonglong2*)&ph[c][kq2 * 4];
            #pragma unroll
            for (int j = 0; j < 4; ++j) {
                float w = Wt[tr + 16 * j][c];
                unsigned long long w2 = fpack2(w, w);
                pfma(acc[j][0], w2, p2.x);
                pfma(acc[j][1], w2, p2.y);
            }
        }
        #pragma unroll
        for (int j = 0; j < 4; ++j) {
            float4 o4;
            punpack(acc[j][0], o4.x, o4.y);
            punpack(acc[j][1], o4.z, o4.w);
            atomicAdd((float4*)&g_Macc[(b0 + tr + 16 * j) * Kc + kq2 * 4], o4);
        }
    }

    // 2b: Nacc[v, k] += sum_c Wt[c][v_local] * th[c][k]
    {
        unsigned long long acc[4][2];
        #pragma unroll
        for (int j = 0; j < 4; ++j) { acc[j][0] = 0ull; acc[j][1] = 0ull; }
        #pragma unroll 8
        for (int c = 0; c < 64; ++c) {
            ulonglong2 t2 = *(const ulonglong2*)&th[c][kq2 * 4];
            #pragma unroll
            for (int j = 0; j < 4; ++j) {
                float w = Wt[c][tr + 16 * j];
                unsigned long long w2 = fpack2(w, w);
                pfma(acc[j][0], w2, t2.x);
                pfma(acc[j][1], w2, t2.y);
            }
        }
        #pragma unroll
        for (int j = 0; j < 4; ++j) {
            float4 o4;
            punpack(acc[j][0], o4.x, o4.y);
            punpack(acc[j][1], o4.z, o4.w);
            atomicAdd((float4*)&g_Nacc[(v0 + tr + 16 * j) * Kc + kq2 * 4], o4);
        }
    }
}

// ---------------------------------------------------------------------------
// K6: epilogue. PDL: input-only preamble loads, wait, then k2/k3 products.
__global__ void __launch_bounds__(256) k6_epi(
        const float* __restrict__ expn,
        const float* __restrict__ expm,
        const unsigned int* __restrict__ idxw,
        float* __restrict__ out) {
    int t = threadIdx.x;
    if (blockIdx.x < 128) {
        int i0 = blockIdx.x * 512 + t;        // unit 0
        int i1 = i0 + 256;                     // unit 1
        float4 e0 = ((const float4*)expn)[i0];   // inputs: safe pre-wait
        float4 e1 = ((const float4*)expn)[i1];
        GDC_WAIT();
        float rho = g_rho, omr = 1.f - rho, rr = rho * g_ratio;
        float4 p0 = ((const float4*)g_phi )[i0];
        float4 p1 = ((const float4*)g_phi )[i1];
        float4 n0 = ((const float4*)g_Nacc)[i0];
        float4 n1 = ((const float4*)g_Nacc)[i1];
        float4 tn0 = make_float4(p0.x*n0.x, p0.y*n0.y, p0.z*n0.z, p0.w*n0.w);
        float4 tn1 = make_float4(p1.x*n1.x, p1.y*n1.y, p1.z*n1.z, p1.w*n1.w);
        ((float4*)(out + OUT_TN))[i0] = tn0;
        ((float4*)(out + OUT_TN))[i1] = tn1;
        int b0 = OUT_NN + i0 * 4;
        out[b0+0] = fmaf(omr, e0.x, rr*tn0.x);
        out[b0+1] = fmaf(omr, e0.y, rr*tn0.y);
        out[b0+2] = fmaf(omr, e0.z, rr*tn0.z);
        out[b0+3] = fmaf(omr, e0.w, rr*tn0.w);
        int b1 = OUT_NN + i1 * 4;
        out[b1+0] = fmaf(omr, e1.x, rr*tn1.x);
        out[b1+1] = fmaf(omr, e1.y, rr*tn1.y);
        out[b1+2] = fmaf(omr, e1.z, rr*tn1.z);
        out[b1+3] = fmaf(omr, e1.w, rr*tn1.w);
    } else {
        GDC_WAIT();                                // needs g_idxstride
        float rho = g_rho, omr = 1.f - rho;
        int i0 = (blockIdx.x - 128) * 512 + t;     // 0..4095 (BK/4) in 2 units
        int i1 = i0 + 256;
        int j0 = i0 * 4, j1 = i1 * 4;
        int d0 = (int)idxw[(j0 >> 6) * g_idxstride];
        int d1 = (int)idxw[(j1 >> 6) * g_idxstride];
        float4 t0 = ((const float4*)g_theta)[i0];
        float4 t1 = ((const float4*)g_theta)[i1];
        float4 m0 = ((const float4*)g_Macc)[i0];
        float4 m1 = ((const float4*)g_Macc)[i1];
        float4 em0 = ((const float4*)expm)[d0 * 16 + ((j0 & 63) >> 2)];
        float4 em1 = ((const float4*)expm)[d1 * 16 + ((j1 & 63) >> 2)];
        float4 tm0 = make_float4(t0.x*m0.x, t0.y*m0.y, t0.z*m0.z, t0.w*m0.w);
        float4 tm1 = make_float4(t1.x*m1.x, t1.y*m1.y, t1.z*m1.z, t1.w*m1.w);
        ((float4*)(out + OUT_TM))[i0] = tm0;
        ((float4*)(out + OUT_TM))[i1] = tm1;
        int b0 = OUT_NM + j0;
        out[b0+0] = fmaf(omr, em0.x, rho*tm0.x);
        out[b0+1] = fmaf(omr, em0.y, rho*tm0.y);
        out[b0+2] = fmaf(omr, em0.z, rho*tm0.z);
        out[b0+3] = fmaf(omr, em0.w, rho*tm0.w);
        int b1 = OUT_NM + j1;
        out[b1+0] = fmaf(omr, em1.x, rho*tm1.x);
        out[b1+1] = fmaf(omr, em1.y, rho*tm1.y);
        out[b1+2] = fmaf(omr, em1.z, rho*tm1.z);
        out[b1+3] = fmaf(omr, em1.w, rho*tm1.w);
    }
}

// ---------------------------------------------------------------------------
extern "C" void kernel_launch(void* const* d_in, const int* in_sizes, int n_in,
                              void* d_out, int out_size) {
    const int*          bow   = (const int*)d_in[0];
    const unsigned int* idxw  = (const unsigned int*)d_in[1];
    const float*        alpha = (const float*)d_in[2];
    const float*        pi    = (const float*)d_in[3];
    const float*        expm  = (const float*)d_in[4];
    const float*        beta  = (const float*)d_in[5];
    const float*        expn  = (const float*)d_in[6];
    const int*          iterp = (const int*)d_in[7];
    const int*          cmp   = (const int*)d_in[8];
    const int*          bcp   = (const int*)d_in[9];
    float* out = (float*)d_out;

    static int smem_set = 0;
    const int k3_smem = 256 * 68 * 4;  // 69632 bytes
    if (!smem_set) {
        cudaFuncSetAttribute(k3_fused, cudaFuncAttributeMaxDynamicSharedMemorySize, k3_smem);
        smem_set = 1;
    }

    cudaLaunchAttribute pdl[1];
    pdl[0].id = cudaLaunchAttributeProgrammaticStreamSerialization;
    pdl[0].val.programmaticStreamSerializationAllowed = 1;

    // k1: normal launch
    k1_denom<<<129, 256>>>(beta, expn, iterp, cmp, bcp, idxw, out);

    // k2: PDL
    {
        cudaLaunchConfig_t cfg = {};
        cfg.gridDim = dim3(272); cfg.blockDim = dim3(256);
        cfg.dynamicSmemBytes = 0; cfg.stream = 0;
        cfg.attrs = pdl; cfg.numAttrs = 1;
        cudaLaunchKernelEx(&cfg, k2_prep, beta, expn, alpha, pi, expm, idxw);
    }
    // k3: PDL
    {
        cudaLaunchConfig_t cfg = {};
        cfg.gridDim = dim3(Vc / 64, Bc / 64); cfg.blockDim = dim3(256);
        cfg.dynamicSmemBytes = k3_smem; cfg.stream = 0;
        cfg.attrs = pdl; cfg.numAttrs = 1;
        cudaLaunchKernelEx(&cfg, k3_fused, bow, out);
    }
    // k6: PDL
    {
        cudaLaunchConfig_t cfg = {};
        cfg.gridDim = dim3(136); cfg.blockDim = dim3(256);
        cfg.dynamicSmemBytes = 0; cfg.stream = 0;
        cfg.attrs = pdl; cfg.numAttrs = 1;
        cudaLaunchKernelEx(&cfg, k6_epi, expn, expm, idxw, out);
    }
}

// round 11
// speedup vs baseline: 1.0559x; 1.0559x over previous
#include <cuda_runtime.h>
#include <math.h>

#define Bc 256
#define Vc 4096
#define Kc 64
#define MINIf 1e-6f

#define VK (Vc*Kc)             /* 262144 */
#define BK (Bc*Kc)             /* 16384  */
#define OUT_TN 0
#define OUT_TM VK
#define OUT_QZ (VK+BK)
#define OUT_NN (VK+BK+1)
#define OUT_NM (VK+BK+1+VK)

// device scratch — everything touched via float4 is explicitly 16B-aligned
__device__ __align__(16) float g_theta[BK];   // theta' published by k3 x==0 blocks
__device__ __align__(16) float g_Nacc[VK];    // zeroed by k6 after reading
__device__ __align__(16) float g_Macc[BK];    // zeroed by k6 after reading
__device__ __align__(16) float g_denom[Kc];   // zero at load; re-zeroed by k1 last block
__device__ __align__(16) float g_rdenom[Kc];
__device__ __align__(16) float g_ldenom[Kc];
__device__ unsigned g_k1cnt;                  // wrap counter, self-resets
__device__ float g_rho;
__device__ float g_ratio;
__device__ int   g_idxstride;

// ---- packed f32x2 helpers (Blackwell FFMA2) --------------------------------
__device__ __forceinline__ void pfma(unsigned long long& acc,
                                     unsigned long long a, unsigned long long b) {
    asm("fma.rn.f32x2 %0, %1, %2, %0;" : "+l"(acc) : "l"(a), "l"(b));
}
__device__ __forceinline__ float psum(unsigned long long v) {
    return __uint_as_float((unsigned)v) + __uint_as_float((unsigned)(v >> 32));
}
__device__ __forceinline__ unsigned long long fpack2(float lo, float hi) {
    unsigned long long r;
    asm("mov.b64 %0, {%1, %2};" : "=l"(r) : "f"(lo), "f"(hi));
    return r;
}
__device__ __forceinline__ void punpack(unsigned long long v, float& lo, float& hi) {
    lo = __uint_as_float((unsigned)v);
    hi = __uint_as_float((unsigned)(v >> 32));
}

// ---------------------------------------------------------------------------
// K1: per-topic denominator + scalars; last-arriving block computes
// rdenom/ldenom and re-zeros g_denom (threadFenceReduction pattern).
// NOTE: red[] is float4-accessed; static __shared__ only guarantees 4B
// alignment once other shared vars exist (s_old) -> explicit __align__(16).
__global__ void __launch_bounds__(256) k1_denom(
        const float* __restrict__ beta,
        const float* __restrict__ expn,
        const int* __restrict__ iterp,
        const int* __restrict__ cmp,
        const int* __restrict__ bcp,
        const unsigned int* __restrict__ idxw,
        float* __restrict__ out) {
    __shared__ __align__(16) float red[16][68];
    __shared__ unsigned s_old;
    int t = threadIdx.x;
    if (blockIdx.x < 128) {
        int cq = t & 15, r = t >> 4;
        int v0 = blockIdx.x * 32;
        float4 b0 = ((const float4*)beta)[(v0 + r     ) * 16 + cq];
        float4 b1 = ((const float4*)beta)[(v0 + r + 16) * 16 + cq];
        float4 e0 = ((const float4*)expn)[(v0 + r     ) * 16 + cq];
        float4 e1 = ((const float4*)expn)[(v0 + r + 16) * 16 + cq];
        float4 a;
        a.x = (b0.x + e0.x) + (b1.x + e1.x);
        a.y = (b0.y + e0.y) + (b1.y + e1.y);
        a.z = (b0.z + e0.z) + (b1.z + e1.z);
        a.w = (b0.w + e0.w) + (b1.w + e1.w);
        *(float4*)&red[r][cq * 4] = a;
        __syncthreads();
        if (t < 64) {
            float s = 0.f;
            #pragma unroll
            for (int r2 = 0; r2 < 16; ++r2) s += red[r2][t];
            atomicAdd(&g_denom[t], s);
        }
    } else if (t == 0) {
        g_rho   = 1.f / powf((float)(iterp[0] + 5), 0.9f);
        g_ratio = (float)cmp[0] / (float)bcp[0];
        // int64-vs-int32 probe: if int64, odd 32-bit words (high halves) are 0.
        bool allz = true;
        for (int i = 1; i < Bc; i += 2)
            if (idxw[i] != 0u) { allz = false; break; }
        g_idxstride = allz ? 2 : 1;
        out[OUT_QZ] = 0.f;
    }

    // last-block tail: finalize rdenom/ldenom, reset denom for next replay
    __syncthreads();
    __threadfence();
    if (t == 0) s_old = atomicInc(&g_k1cnt, 128u);   // wraps 128 -> 0
    __syncthreads();
    if (s_old == 128u && t < 64) {
        float d = g_denom[t];
        g_rdenom[t] = __fdividef(1.f, d);
        g_ldenom[t] = __logf(d);
        g_denom[t]  = 0.f;
    }
}

// ---------------------------------------------------------------------------
// K3 fused: per block 64b x 64v tile; builds its own phi/theta tiles in smem
// (denominator-cancelled formulation: th' = theta/denom, ph = beta+expn).
// Phase 1 S/A GEMM + w/entropy; phase 2 rank-64 GEMMs -> Macc/Nacc atomics.
__global__ void __launch_bounds__(256, 2)
k3_fused(const int* __restrict__ bow,
         const float* __restrict__ beta,
         const float* __restrict__ expn,
         const float* __restrict__ alpha,
         const float* __restrict__ pi,
         const float* __restrict__ expm,
         const unsigned int* __restrict__ idxw,
         float* __restrict__ out) {
    extern __shared__ float sm3[];
    float (*th)[68]  = (float(*)[68])(sm3);
    float (*thL)[68] = (float(*)[68])(sm3 + 64 * 68);   // becomes Wt in phase 2
    float (*ph)[68]  = (float(*)[68])(sm3 + 128 * 68);
    float (*phL)[68] = (float(*)[68])(sm3 + 192 * 68);
    float (*Wt)[68]  = thL;

    int t = threadIdx.x;
    int v0 = blockIdx.x * 64;
    int b0 = blockIdx.y * 64;

    int tv = t & 15;       // v_local = tv + 16*vi
    int tb = t >> 4;       // b_local = tb + 16*bi

    // preamble: scattered bow loads (latency hidden under tile fill)
    int cnt[4][4];
    #pragma unroll
    for (int bi = 0; bi < 4; ++bi)
        #pragma unroll
        for (int vi = 0; vi < 4; ++vi)
            cnt[bi][vi] = bow[(b0 + tb + 16 * bi) * Vc + v0 + tv + 16 * vi];

    int stride = g_idxstride;
    // tile fill: 4 iterations cover 64 rows x 16 quads for both v and b tiles
    #pragma unroll
    for (int j = 0; j < 4; ++j) {
        int i = j * 256 + t;
        int r = i >> 4, cq = i & 15;
        // v-tile: ph = beta+expn (raw), phL = ph*log(ph)
        float4 b4 = ((const float4*)beta)[(v0 + r) * 16 + cq];
        float4 e4 = ((const float4*)expn)[(v0 + r) * 16 + cq];
        float4 p;
        p.x = b4.x + e4.x; p.y = b4.y + e4.y;
        p.z = b4.z + e4.z; p.w = b4.w + e4.w;
        float4 pl;
        pl.x = p.x * __logf(p.x);
        pl.y = p.y * __logf(p.y);
        pl.z = p.z * __logf(p.z);
        pl.w = p.w * __logf(p.w);
        *(float4*)&ph [r][cq * 4] = p;
        *(float4*)&phL[r][cq * 4] = pl;
        // b-tile: traw = alpha*pi[d]+em[d]; th' = traw*rd; thL' = th'*(log(traw)-ld)
        int d = (int)idxw[(b0 + r) * stride];
        float4 al = ((const float4*)alpha   )[cq];
        float4 pp = ((const float4*)pi      )[d * 16 + cq];
        float4 em = ((const float4*)expm    )[d * 16 + cq];
        float4 rd = ((const float4*)g_rdenom)[cq];
        float4 ld = ((const float4*)g_ldenom)[cq];
        float4 traw, tt, tl;
        traw.x = fmaf(al.x, pp.x, em.x);
        traw.y = fmaf(al.y, pp.y, em.y);
        traw.z = fmaf(al.z, pp.z, em.z);
        traw.w = fmaf(al.w, pp.w, em.w);
        tt.x = traw.x * rd.x; tt.y = traw.y * rd.y;
        tt.z = traw.z * rd.z; tt.w = traw.w * rd.w;
        tl.x = tt.x * (__logf(traw.x) - ld.x);
        tl.y = tt.y * (__logf(traw.y) - ld.y);
        tl.z = tt.z * (__logf(traw.z) - ld.z);
        tl.w = tt.w * (__logf(traw.w) - ld.w);
        *(float4*)&th [r][cq * 4] = tt;
        *(float4*)&thL[r][cq * 4] = tl;
        // one v-block column publishes theta' for k6
        if (blockIdx.x == 0)
            ((float4*)g_theta)[(b0 + r) * 16 + cq] = tt;
    }
    __syncthreads();

    unsigned long long S2[4][4], A2[4][4];
    #pragma unroll
    for (int bi = 0; bi < 4; ++bi)
        #pragma unroll
        for (int vi = 0; vi < 4; ++vi) { S2[bi][vi] = 0ull; A2[bi][vi] = 0ull; }

    #pragma unroll 4
    for (int kq = 0; kq < 16; ++kq) {
        ulonglong2 P[4], Q[4];
        #pragma unroll
        for (int vi = 0; vi < 4; ++vi) {
            P[vi] = *(const ulonglong2*)&ph [tv + 16 * vi][kq * 4];
            Q[vi] = *(const ulonglong2*)&phL[tv + 16 * vi][kq * 4];
        }
        #pragma unroll
        for (int bi = 0; bi < 4; ++bi) {
            ulonglong2 T = *(const ulonglong2*)&th [tb + 16 * bi][kq * 4];
            ulonglong2 L = *(const ulonglong2*)&thL[tb + 16 * bi][kq * 4];
            #pragma unroll
            for (int vi = 0; vi < 4; ++vi) {
                pfma(S2[bi][vi], T.x, P[vi].x);
                pfma(S2[bi][vi], T.y, P[vi].y);
                pfma(A2[bi][vi], L.x, P[vi].x);
                pfma(A2[bi][vi], L.y, P[vi].y);
                pfma(A2[bi][vi], T.x, Q[vi].x);
                pfma(A2[bi][vi], T.y, Q[vi].y);
            }
        }
    }

    // epilogue of phase 1: w, entropy
    float wv[4][4];
    float ent = 0.f;
    #pragma unroll
    for (int bi = 0; bi < 4; ++bi) {
        #pragma unroll
        for (int vi = 0; vi < 4; ++vi) {
            float S = psum(S2[bi][vi]);
            float A = psum(A2[bi][vi]);
            float sp = S + MINIf;
            float r  = __fdividef(1.f, sp);
            int c = cnt[bi][vi];
            wv[bi][vi] = (float)c * r;
            if (c > 0)
                ent += (A - S * __logf(sp)) * r;
        }
    }

    // block entropy reduction
    #pragma unroll
    for (int o = 16; o; o >>= 1)
        ent += __shfl_xor_sync(0xFFFFFFFFu, ent, o);
    __shared__ float ered[8];
    if ((t & 31) == 0) ered[t >> 5] = ent;

    __syncthreads();   // all thL reads done; ered visible
    if (t == 0) {
        float s = 0.f;
        #pragma unroll
        for (int w = 0; w < 8; ++w) s += ered[w];
        atomicAdd(&out[OUT_QZ], s);
    }

    // stage W into smem (overwrites thL)
    #pragma unroll
    for (int bi = 0; bi < 4; ++bi)
        #pragma unroll
        for (int vi = 0; vi < 4; ++vi)
            Wt[tb + 16 * bi][tv + 16 * vi] = wv[bi][vi];
    __syncthreads();

    // ---- phase 2 ----
    int kq2 = t & 15;            // k = kq2*4 .. +3
    int tr  = t >> 4;            // row group: tr + 16*j

    // 2a: Macc[b, k] += sum_c Wt[b_local][c] * ph[c][k]    (ph = phi_raw)
    {
        unsigned long long acc[4][2];
        #pragma unroll
        for (int j = 0; j < 4; ++j) { acc[j][0] = 0ull; acc[j][1] = 0ull; }
        #pragma unroll 8
        for (int c = 0; c < 64; ++c) {
            ulonglong2 p2 = *(const ulonglong2*)&ph[c][kq2 * 4];
            #pragma unroll
            for (int j = 0; j < 4; ++j) {
                float w = Wt[tr + 16 * j][c];
                unsigned long long w2 = fpack2(w, w);
                pfma(acc[j][0], w2, p2.x);
                pfma(acc[j][1], w2, p2.y);
            }
        }
        #pragma unroll
        for (int j = 0; j < 4; ++j) {
            float4 o4;
            punpack(acc[j][0], o4.x, o4.y);
            punpack(acc[j][1], o4.z, o4.w);
            atomicAdd((float4*)&g_Macc[(b0 + tr + 16 * j) * Kc + kq2 * 4], o4);
        }
    }

    // 2b: Nacc[v, k] += sum_c Wt[c][v_local] * th[c][k]    (th = theta')
    {
        unsigned long long acc[4][2];
        #pragma unroll
        for (int j = 0; j < 4; ++j) { acc[j][0] = 0ull; acc[j][1] = 0ull; }
        #pragma unroll 8
        for (int c = 0; c < 64; ++c) {
            ulonglong2 t2 = *(const ulonglong2*)&th[c][kq2 * 4];
            #pragma unroll
            for (int j = 0; j < 4; ++j) {
                float w = Wt[c][tr + 16 * j];
                unsigned long long w2 = fpack2(w, w);
                pfma(acc[j][0], w2, t2.x);
                pfma(acc[j][1], w2, t2.y);
            }
        }
        #pragma unroll
        for (int j = 0; j < 4; ++j) {
            float4 o4;
            punpack(acc[j][0], o4.x, o4.y);
            punpack(acc[j][1], o4.z, o4.w);
            atomicAdd((float4*)&g_Nacc[(v0 + tr + 16 * j) * Kc + kq2 * 4], o4);
        }
    }
}

// ---------------------------------------------------------------------------
// K6: epilogue; recomputes phi_raw = beta+expn; zeroes Nacc/Macc after use.
__global__ void __launch_bounds__(256) k6_epi(
        const float* __restrict__ beta,
        const float* __restrict__ expn,
        const float* __restrict__ expm,
        const unsigned int* __restrict__ idxw,
        float* __restrict__ out) {
    float rho = g_rho, omr = 1.f - rho, rr = rho * g_ratio;
    int t = threadIdx.x;
    const float4 z4 = make_float4(0.f, 0.f, 0.f, 0.f);
    if (blockIdx.x < 128) {
        int i0 = blockIdx.x * 512 + t;        // unit 0
        int i1 = i0 + 256;                     // unit 1
        float4 b0v = ((const float4*)beta)[i0];
        float4 b1v = ((const float4*)beta)[i1];
        float4 e0 = ((const float4*)expn)[i0];
        float4 e1 = ((const float4*)expn)[i1];
        float4 n0 = ((const float4*)g_Nacc)[i0];
        float4 n1 = ((const float4*)g_Nacc)[i1];
        float4 tn0, tn1;
        tn0.x = (b0v.x + e0.x) * n0.x; tn0.y = (b0v.y + e0.y) * n0.y;
        tn0.z = (b0v.z + e0.z) * n0.z; tn0.w = (b0v.w + e0.w) * n0.w;
        tn1.x = (b1v.x + e1.x) * n1.x; tn1.y = (b1v.y + e1.y) * n1.y;
        tn1.z = (b1v.z + e1.z) * n1.z; tn1.w = (b1v.w + e1.w) * n1.w;
        ((float4*)g_Nacc)[i0] = z4;            // reset for next replay
        ((float4*)g_Nacc)[i1] = z4;
        ((float4*)(out + OUT_TN))[i0] = tn0;
        ((float4*)(out + OUT_TN))[i1] = tn1;
        int c0 = OUT_NN + i0 * 4;
        out[c0+0] = fmaf(omr, e0.x, rr*tn0.x);
        out[c0+1] = fmaf(omr, e0.y, rr*tn0.y);
        out[c0+2] = fmaf(omr, e0.z, rr*tn0.z);
        out[c0+3] = fmaf(omr, e0.w, rr*tn0.w);
        int c1 = OUT_NN + i1 * 4;
        out[c1+0] = fmaf(omr, e1.x, rr*tn1.x);
        out[c1+1] = fmaf(omr, e1.y, rr*tn1.y);
        out[c1+2] = fmaf(omr, e1.z, rr*tn1.z);
        out[c1+3] = fmaf(omr, e1.w, rr*tn1.w);
    } else {
        int stride = g_idxstride;
        int i0 = (blockIdx.x - 128) * 512 + t;     // 0..4095 (BK/4) in 2 units
        int i1 = i0 + 256;
        int j0 = i0 * 4, j1 = i1 * 4;
        int d0 = (int)idxw[(j0 >> 6) * stride];
        int d1 = (int)idxw[(j1 >> 6) * stride];
        float4 t0 = ((const float4*)g_theta)[i0];
        float4 t1 = ((const float4*)g_theta)[i1];
        float4 m0 = ((const float4*)g_Macc)[i0];
        float4 m1 = ((const float4*)g_Macc)[i1];
        float4 em0 = ((const float4*)expm)[d0 * 16 + (i0 & 15)];
        float4 em1 = ((const float4*)expm)[d1 * 16 + (i1 & 15)];
        float4 tm0 = make_float4(t0.x*m0.x, t0.y*m0.y, t0.z*m0.z, t0.w*m0.w);
        float4 tm1 = make_float4(t1.x*m1.x, t1.y*m1.y, t1.z*m1.z, t1.w*m1.w);
        ((float4*)g_Macc)[i0] = z4;                // reset for next replay
        ((float4*)g_Macc)[i1] = z4;
        ((float4*)(out + OUT_TM))[i0] = tm0;
        ((float4*)(out + OUT_TM))[i1] = tm1;
        int c0 = OUT_NM + j0;
        out[c0+0] = fmaf(omr, em0.x, rho*tm0.x);
        out[c0+1] = fmaf(omr, em0.y, rho*tm0.y);
        out[c0+2] = fmaf(omr, em0.z, rho*tm0.z);
        out[c0+3] = fmaf(omr, em0.w, rho*tm0.w);
        int c1 = OUT_NM + j1;
        out[c1+0] = fmaf(omr, em1.x, rho*tm1.x);
        out[c1+1] = fmaf(omr, em1.y, rho*tm1.y);
        out[c1+2] = fmaf(omr, em1.z, rho*tm1.z);
        out[c1+3] = fmaf(omr, em1.w, rho*tm1.w);
    }
}

// ---------------------------------------------------------------------------
extern "C" void kernel_launch(void* const* d_in, const int* in_sizes, int n_in,
                              void* d_out, int out_size) {
    const int*          bow   = (const int*)d_in[0];
    const unsigned int* idxw  = (const unsigned int*)d_in[1];
    const float*        alpha = (const float*)d_in[2];
    const float*        pi    = (const float*)d_in[3];
    const float*        expm  = (const float*)d_in[4];
    const float*        beta  = (const float*)d_in[5];
    const float*        expn  = (const float*)d_in[6];
    const int*          iterp = (const int*)d_in[7];
    const int*          cmp   = (const int*)d_in[8];
    const int*          bcp   = (const int*)d_in[9];
    float* out = (float*)d_out;

    static int smem_set = 0;
    const int k3_smem = 256 * 68 * 4;  // 69632 bytes
    if (!smem_set) {
        cudaFuncSetAttribute(k3_fused, cudaFuncAttributeMaxDynamicSharedMemorySize, k3_smem);
        smem_set = 1;
    }

    k1_denom<<<129, 256>>>(beta, expn, iterp, cmp, bcp, idxw, out);
    dim3 g3(Vc / 64, Bc / 64);
    k3_fused<<<g3, 256, k3_smem>>>(bow, beta, expn, alpha, pi, expm, idxw, out);
    k6_epi<<<136, 256>>>(beta, expn, expm, idxw, out);
}

// round 12
// speedup vs baseline: 1.0645x; 1.0082x over previous
#include <cuda_runtime.h>
#include <math.h>

#define Bc 256
#define Vc 4096
#define Kc 64
#define MINIf 1e-6f

#define VK (Vc*Kc)             /* 262144 */
#define BK (Bc*Kc)             /* 16384  */
#define OUT_TN 0
#define OUT_TM VK
#define OUT_QZ (VK+BK)
#define OUT_NN (VK+BK+1)
#define OUT_NM (VK+BK+1+VK)

#define NBLK 256

// device scratch — float4-accessed arrays explicitly 16B-aligned
__device__ __align__(16) float g_theta[BK];   // theta' published by x==0 blocks
__device__ __align__(16) float g_Nacc[VK];    // self-reset in epilogue
__device__ __align__(16) float g_Macc[BK];    // self-reset in epilogue
__device__ __align__(16) float g_denom[Kc];   // self-reset in epilogue
__device__ unsigned g_barcnt[2];              // monotone epoch counters
__device__ unsigned g_barrel[2];
__device__ float g_rho;
__device__ float g_ratio;

// ---- packed f32x2 helpers (Blackwell FFMA2) --------------------------------
__device__ __forceinline__ void pfma(unsigned long long& acc,
                                     unsigned long long a, unsigned long long b) {
    asm("fma.rn.f32x2 %0, %1, %2, %0;" : "+l"(acc) : "l"(a), "l"(b));
}
__device__ __forceinline__ float psum(unsigned long long v) {
    return __uint_as_float((unsigned)v) + __uint_as_float((unsigned)(v >> 32));
}
__device__ __forceinline__ unsigned long long fpack2(float lo, float hi) {
    unsigned long long r;
    asm("mov.b64 %0, {%1, %2};" : "=l"(r) : "f"(lo), "f"(hi));
    return r;
}
__device__ __forceinline__ void punpack(unsigned long long v, float& lo, float& hi) {
    lo = __uint_as_float((unsigned)v);
    hi = __uint_as_float((unsigned)(v >> 32));
}

// ---- grid barrier (all NBLK blocks co-resident: 2/SM x 148 = 296 >= 256) ----
// Epoch scheme survives graph replays without reset: arrivals are monotone;
// release epoch e means e*NBLK arrivals have completed.
__device__ __forceinline__ void gridbar(int id) {
    __syncthreads();
    if (threadIdx.x == 0) {
        __threadfence();
        unsigned arrive = atomicAdd(&g_barcnt[id], 1u) + 1u;
        unsigned epoch = (arrive + NBLK - 1u) / NBLK;
        if (arrive == epoch * NBLK) {
            atomicAdd(&g_barrel[id], 1u);
        } else {
            while (atomicAdd(&g_barrel[id], 0u) < epoch) __nanosleep(64);
        }
    }
    __syncthreads();
}

// ---------------------------------------------------------------------------
// Mono-kernel: denominator partials -> bar0 -> scale tiles -> S/A GEMM +
// w/entropy -> rank-64 GEMMs (atomics) -> bar1 -> full epilogue + self-reset.
__global__ void __launch_bounds__(256, 2)
mono(const int* __restrict__ bow,
     const unsigned int* __restrict__ idxw,
     const float* __restrict__ alpha,
     const float* __restrict__ pi,
     const float* __restrict__ expm,
     const float* __restrict__ beta,
     const float* __restrict__ expn,
     const int* __restrict__ iterp,
     const int* __restrict__ cmp,
     const int* __restrict__ bcp,
     float* __restrict__ out) {
    extern __shared__ float sm3[];
    float (*th)[68]  = (float(*)[68])(sm3);
    float (*thL)[68] = (float(*)[68])(sm3 + 64 * 68);   // becomes Wt in phase 2
    float (*ph)[68]  = (float(*)[68])(sm3 + 128 * 68);
    float (*phL)[68] = (float(*)[68])(sm3 + 192 * 68);
    float (*Wt)[68]  = thL;

    __shared__ __align__(16) float red[16][68];
    __shared__ __align__(16) float srd[64];
    __shared__ __align__(16) float sld[64];
    __shared__ float ered[8];
    __shared__ int s_nz;

    int t = threadIdx.x;
    int rank = blockIdx.y * 64 + blockIdx.x;
    int v0 = blockIdx.x * 64;
    int b0 = blockIdx.y * 64;
    int tv = t & 15;       // v_local = tv + 16*vi
    int tb = t >> 4;       // b_local = tb + 16*bi

    // ---- phase A: everything that needs no denominator ----
    // bow loads first (longest-latency scattered loads)
    int cnt[4][4];
    #pragma unroll
    for (int bi = 0; bi < 4; ++bi)
        #pragma unroll
        for (int vi = 0; vi < 4; ++vi)
            cnt[bi][vi] = bow[(b0 + tb + 16 * bi) * Vc + v0 + tv + 16 * vi];

    if (t == 0) s_nz = 0;

    // denominator partial: this block sums rows [rank*16, rank*16+16)
    {
        int cq = t & 15, rr = t >> 4;
        int vp = rank * 16;
        float4 db = ((const float4*)beta)[(vp + rr) * 16 + cq];
        float4 de = ((const float4*)expn)[(vp + rr) * 16 + cq];
        __syncthreads();                       // s_nz init visible
        if (t < 128 && idxw[2 * t + 1] != 0u) atomicOr(&s_nz, 1);
        float4 a;
        a.x = db.x + de.x; a.y = db.y + de.y;
        a.z = db.z + de.z; a.w = db.w + de.w;
        *(float4*)&red[rr][cq * 4] = a;
        __syncthreads();
        if (t < 64) {
            float s = 0.f;
            #pragma unroll
            for (int r2 = 0; r2 < 16; ++r2) s += red[r2][t];
            atomicAdd(&g_denom[t], s);
        }
        if (rank == 255 && t == 0) {
            g_rho   = 1.f / powf((float)(iterp[0] + 5), 0.9f);
            g_ratio = (float)cmp[0] / (float)bcp[0];
            out[OUT_QZ] = 0.f;
        }
    }
    int stride = s_nz ? 1 : 2;    // int32 vs int64 batch_indices

    // tile fill (NO denominator needed): ph=beta+expn, phL=ph*log(ph),
    // th_pre=traw, thL_pre=traw*log(traw)
    #pragma unroll
    for (int j = 0; j < 4; ++j) {
        int i = j * 256 + t;
        int r = i >> 4, cq = i & 15;
        float4 b4 = ((const float4*)beta)[(v0 + r) * 16 + cq];
        float4 e4 = ((const float4*)expn)[(v0 + r) * 16 + cq];
        float4 p;
        p.x = b4.x + e4.x; p.y = b4.y + e4.y;
        p.z = b4.z + e4.z; p.w = b4.w + e4.w;
        float4 pl;
        pl.x = p.x * __logf(p.x);
        pl.y = p.y * __logf(p.y);
        pl.z = p.z * __logf(p.z);
        pl.w = p.w * __logf(p.w);
        *(float4*)&ph [r][cq * 4] = p;
        *(float4*)&phL[r][cq * 4] = pl;
        int d = (int)idxw[(b0 + r) * stride];
        float4 al = ((const float4*)alpha)[cq];
        float4 pp = ((const float4*)pi   )[d * 16 + cq];
        float4 em = ((const float4*)expm )[d * 16 + cq];
        float4 traw, tl;
        traw.x = fmaf(al.x, pp.x, em.x);
        traw.y = fmaf(al.y, pp.y, em.y);
        traw.z = fmaf(al.z, pp.z, em.z);
        traw.w = fmaf(al.w, pp.w, em.w);
        tl.x = traw.x * __logf(traw.x);
        tl.y = traw.y * __logf(traw.y);
        tl.z = traw.z * __logf(traw.z);
        tl.w = traw.w * __logf(traw.w);
        *(float4*)&th [r][cq * 4] = traw;
        *(float4*)&thL[r][cq * 4] = tl;
    }

    // ---- barrier 0: all denominator partials in ----
    gridbar(0);

    if (t < 64) {
        float d = g_denom[t];
        srd[t] = __fdividef(1.f, d);
        sld[t] = __logf(d);
    }
    __syncthreads();

    // scale theta tiles: th' = traw*rd ; thL' = (trawL - traw*ld)*rd
    #pragma unroll
    for (int j = 0; j < 4; ++j) {
        int i = j * 256 + t;
        int r = i >> 4, cq = i & 15;
        float4 tp  = *(const float4*)&th [r][cq * 4];
        float4 tlp = *(const float4*)&thL[r][cq * 4];
        float4 rd = *(const float4*)&srd[cq * 4];
        float4 ld = *(const float4*)&sld[cq * 4];
        float4 tt, tl;
        tt.x = tp.x * rd.x; tt.y = tp.y * rd.y;
        tt.z = tp.z * rd.z; tt.w = tp.w * rd.w;
        tl.x = (tlp.x - tp.x * ld.x) * rd.x;
        tl.y = (tlp.y - tp.y * ld.y) * rd.y;
        tl.z = (tlp.z - tp.z * ld.z) * rd.z;
        tl.w = (tlp.w - tp.w * ld.w) * rd.w;
        *(float4*)&th [r][cq * 4] = tt;
        *(float4*)&thL[r][cq * 4] = tl;
        if (blockIdx.x == 0)
            ((float4*)g_theta)[(b0 + r) * 16 + cq] = tt;
    }
    __syncthreads();

    // ---- phase 1: S/A GEMM ----
    unsigned long long S2[4][4], A2[4][4];
    #pragma unroll
    for (int bi = 0; bi < 4; ++bi)
        #pragma unroll
        for (int vi = 0; vi < 4; ++vi) { S2[bi][vi] = 0ull; A2[bi][vi] = 0ull; }

    #pragma unroll 4
    for (int kq = 0; kq < 16; ++kq) {
        ulonglong2 P[4], Q[4];
        #pragma unroll
        for (int vi = 0; vi < 4; ++vi) {
            P[vi] = *(const ulonglong2*)&ph [tv + 16 * vi][kq * 4];
            Q[vi] = *(const ulonglong2*)&phL[tv + 16 * vi][kq * 4];
        }
        #pragma unroll
        for (int bi = 0; bi < 4; ++bi) {
            ulonglong2 T = *(const ulonglong2*)&th [tb + 16 * bi][kq * 4];
            ulonglong2 L = *(const ulonglong2*)&thL[tb + 16 * bi][kq * 4];
            #pragma unroll
            for (int vi = 0; vi < 4; ++vi) {
                pfma(S2[bi][vi], T.x, P[vi].x);
                pfma(S2[bi][vi], T.y, P[vi].y);
                pfma(A2[bi][vi], L.x, P[vi].x);
                pfma(A2[bi][vi], L.y, P[vi].y);
                pfma(A2[bi][vi], T.x, Q[vi].x);
                pfma(A2[bi][vi], T.y, Q[vi].y);
            }
        }
    }

    // w, entropy
    float wv[4][4];
    float ent = 0.f;
    #pragma unroll
    for (int bi = 0; bi < 4; ++bi) {
        #pragma unroll
        for (int vi = 0; vi < 4; ++vi) {
            float S = psum(S2[bi][vi]);
            float A = psum(A2[bi][vi]);
            float sp = S + MINIf;
            float r  = __fdividef(1.f, sp);
            int c = cnt[bi][vi];
            wv[bi][vi] = (float)c * r;
            if (c > 0)
                ent += (A - S * __logf(sp)) * r;
        }
    }

    #pragma unroll
    for (int o = 16; o; o >>= 1)
        ent += __shfl_xor_sync(0xFFFFFFFFu, ent, o);
    if ((t & 31) == 0) ered[t >> 5] = ent;

    __syncthreads();
    if (t == 0) {
        float s = 0.f;
        #pragma unroll
        for (int w = 0; w < 8; ++w) s += ered[w];
        atomicAdd(&out[OUT_QZ], s);
    }

    // stage W into smem (overwrites thL)
    #pragma unroll
    for (int bi = 0; bi < 4; ++bi)
        #pragma unroll
        for (int vi = 0; vi < 4; ++vi)
            Wt[tb + 16 * bi][tv + 16 * vi] = wv[bi][vi];
    __syncthreads();

    // ---- phase 2 ----
    int kq2 = t & 15;
    int tr  = t >> 4;

    // 2a: Macc[b, k] += sum_c Wt[b_local][c] * ph[c][k]
    {
        unsigned long long acc[4][2];
        #pragma unroll
        for (int j = 0; j < 4; ++j) { acc[j][0] = 0ull; acc[j][1] = 0ull; }
        #pragma unroll 8
        for (int c = 0; c < 64; ++c) {
            ulonglong2 p2 = *(const ulonglong2*)&ph[c][kq2 * 4];
            #pragma unroll
            for (int j = 0; j < 4; ++j) {
                float w = Wt[tr + 16 * j][c];
                unsigned long long w2 = fpack2(w, w);
                pfma(acc[j][0], w2, p2.x);
                pfma(acc[j][1], w2, p2.y);
            }
        }
        #pragma unroll
        for (int j = 0; j < 4; ++j) {
            float4 o4;
            punpack(acc[j][0], o4.x, o4.y);
            punpack(acc[j][1], o4.z, o4.w);
            atomicAdd((float4*)&g_Macc[(b0 + tr + 16 * j) * Kc + kq2 * 4], o4);
        }
    }

    // 2b: Nacc[v, k] += sum_c Wt[c][v_local] * th[c][k]
    {
        unsigned long long acc[4][2];
        #pragma unroll
        for (int j = 0; j < 4; ++j) { acc[j][0] = 0ull; acc[j][1] = 0ull; }
        #pragma unroll 8
        for (int c = 0; c < 64; ++c) {
            ulonglong2 t2 = *(const ulonglong2*)&th[c][kq2 * 4];
            #pragma unroll
            for (int j = 0; j < 4; ++j) {
                float w = Wt[c][tr + 16 * j];
                unsigned long long w2 = fpack2(w, w);
                pfma(acc[j][0], w2, t2.x);
                pfma(acc[j][1], w2, t2.y);
            }
        }
        #pragma unroll
        for (int j = 0; j < 4; ++j) {
            float4 o4;
            punpack(acc[j][0], o4.x, o4.y);
            punpack(acc[j][1], o4.z, o4.w);
            atomicAdd((float4*)&g_Nacc[(v0 + tr + 16 * j) * Kc + kq2 * 4], o4);
        }
    }

    // ---- barrier 1: all accumulators complete ----
    gridbar(1);

    // ---- epilogue, distributed over all 65536 threads (L2-hot) ----
    float rho = g_rho, omr = 1.f - rho, rr2 = rho * g_ratio;
    const float4 z4 = make_float4(0.f, 0.f, 0.f, 0.f);
    int gid = rank * 256 + t;                 // 0..65535 == VK/4

    {
        float4 b4 = ((const float4*)beta)[gid];
        float4 e4 = ((const float4*)expn)[gid];
        float4 n4 = ((const float4*)g_Nacc)[gid];
        float4 tn;
        tn.x = (b4.x + e4.x) * n4.x; tn.y = (b4.y + e4.y) * n4.y;
        tn.z = (b4.z + e4.z) * n4.z; tn.w = (b4.w + e4.w) * n4.w;
        ((float4*)g_Nacc)[gid] = z4;           // self-reset for next replay
        ((float4*)(out + OUT_TN))[gid] = tn;
        int c0 = OUT_NN + gid * 4;
        out[c0+0] = fmaf(omr, e4.x, rr2*tn.x);
        out[c0+1] = fmaf(omr, e4.y, rr2*tn.y);
        out[c0+2] = fmaf(omr, e4.z, rr2*tn.z);
        out[c0+3] = fmaf(omr, e4.w, rr2*tn.w);
    }

    if (gid < BK / 4) {                        // 4096 float4 units for TM/NM
        int j = gid * 4;
        int b = j >> 6;
        int d = (int)idxw[b * stride];
        float4 t4 = ((const float4*)g_theta)[gid];
        float4 m4 = ((const float4*)g_Macc)[gid];
        float4 em = ((const float4*)expm)[d * 16 + (gid & 15)];
        float4 tm = make_float4(t4.x*m4.x, t4.y*m4.y, t4.z*m4.z, t4.w*m4.w);
        ((float4*)g_Macc)[gid] = z4;           // self-reset
        ((float4*)(out + OUT_TM))[gid] = tm;
        int c0 = OUT_NM + j;
        out[c0+0] = fmaf(omr, em.x, rho*tm.x);
        out[c0+1] = fmaf(omr, em.y, rho*tm.y);
        out[c0+2] = fmaf(omr, em.z, rho*tm.z);
        out[c0+3] = fmaf(omr, em.w, rho*tm.w);
    }

    if (rank == 0 && t < 64)
        g_denom[t] = 0.f;                      // self-reset
}

// ---------------------------------------------------------------------------
extern "C" void kernel_launch(void* const* d_in, const int* in_sizes, int n_in,
                              void* d_out, int out_size) {
    const int*          bow   = (const int*)d_in[0];
    const unsigned int* idxw  = (const unsigned int*)d_in[1];
    const float*        alpha = (const float*)d_in[2];
    const float*        pi    = (const float*)d_in[3];
    const float*        expm  = (const float*)d_in[4];
    const float*        beta  = (const float*)d_in[5];
    const float*        expn  = (const float*)d_in[6];
    const int*          iterp = (const int*)d_in[7];
    const int*          cmp   = (const int*)d_in[8];
    const int*          bcp   = (const int*)d_in[9];
    float* out = (float*)d_out;

    static int smem_set = 0;
    const int k_smem = 256 * 68 * 4;  // 69632 bytes dynamic
    if (!smem_set) {
        cudaFuncSetAttribute(mono, cudaFuncAttributeMaxDynamicSharedMemorySize, k_smem);
        smem_set = 1;
    }

    dim3 g(Vc / 64, Bc / 64);   // (64,4) = 256 blocks, all co-resident (2/SM)
    mono<<<g, 256, k_smem>>>(bow, idxw, alpha, pi, expm, beta, expn,
                             iterp, cmp, bcp, out);
}

// round 13
// speedup vs baseline: 1.0656x; 1.0010x over previous
#include <cuda_runtime.h>
#include <math.h>

#define Bc 256
#define Vc 4096
#define Kc 64
#define MINIf 1e-6f

#define VK (Vc*Kc)             /* 262144 */
#define BK (Bc*Kc)             /* 16384  */
#define OUT_TN 0
#define OUT_TM VK
#define OUT_QZ (VK+BK)
#define OUT_NN (VK+BK+1)
#define OUT_NM (VK+BK+1+VK)

#define NBLK 256

// device scratch — float4-accessed arrays explicitly 16B-aligned
__device__ __align__(16) float g_theta[BK];   // theta' published by x==0 blocks
__device__ __align__(16) float g_Nacc[VK];    // self-reset in epilogue
__device__ __align__(16) float g_Macc[BK];    // self-reset in epilogue
__device__ __align__(16) float g_denom[Kc];   // self-reset post-bar1
__device__ unsigned g_barcnt[2];              // monotone epoch counters
__device__ unsigned g_barrel[2];
__device__ float g_rho;
__device__ float g_ratio;

// ---- packed f32x2 helpers (Blackwell FFMA2) --------------------------------
__device__ __forceinline__ void pfma(unsigned long long& acc,
                                     unsigned long long a, unsigned long long b) {
    asm("fma.rn.f32x2 %0, %1, %2, %0;" : "+l"(acc) : "l"(a), "l"(b));
}
__device__ __forceinline__ float psum(unsigned long long v) {
    return __uint_as_float((unsigned)v) + __uint_as_float((unsigned)(v >> 32));
}
__device__ __forceinline__ unsigned long long fpack2(float lo, float hi) {
    unsigned long long r;
    asm("mov.b64 %0, {%1, %2};" : "=l"(r) : "f"(lo), "f"(hi));
    return r;
}
__device__ __forceinline__ void punpack(unsigned long long v, float& lo, float& hi) {
    lo = __uint_as_float((unsigned)v);
    hi = __uint_as_float((unsigned)(v >> 32));
}

// ---- split grid barrier (all NBLK blocks co-resident: 2/SM) -----------------
// Epoch scheme survives graph replays (monotone counters, no reset needed).
// arrive: returns this launch's epoch. wait: spins until release >= epoch.
__device__ __forceinline__ unsigned bar_arrive(int id) {
    __syncthreads();
    __shared__ unsigned s_ep[2];
    if (threadIdx.x == 0) {
        __threadfence();
        unsigned arrive = atomicAdd(&g_barcnt[id], 1u) + 1u;
        unsigned epoch = (arrive + NBLK - 1u) / NBLK;
        if (arrive == epoch * NBLK)
            atomicAdd(&g_barrel[id], 1u);
        s_ep[id] = epoch;
    }
    __syncthreads();
    return s_ep[id];
}
__device__ __forceinline__ void bar_wait(int id, unsigned epoch) {
    if (threadIdx.x == 0) {
        while (atomicAdd(&g_barrel[id], 0u) < epoch) __nanosleep(64);
    }
    __syncthreads();
}

// ---------------------------------------------------------------------------
__global__ void __launch_bounds__(256, 2)
mono(const int* __restrict__ bow,
     const unsigned int* __restrict__ idxw,
     const float* __restrict__ alpha,
     const float* __restrict__ pi,
     const float* __restrict__ expm,
     const float* __restrict__ beta,
     const float* __restrict__ expn,
     const int* __restrict__ iterp,
     const int* __restrict__ cmp,
     const int* __restrict__ bcp,
     float* __restrict__ out) {
    extern __shared__ float sm3[];
    float (*th)[68]  = (float(*)[68])(sm3);
    float (*thL)[68] = (float(*)[68])(sm3 + 64 * 68);   // becomes Wt in phase 2
    float (*ph)[68]  = (float(*)[68])(sm3 + 128 * 68);
    float (*phL)[68] = (float(*)[68])(sm3 + 192 * 68);
    float (*Wt)[68]  = thL;

    __shared__ __align__(16) float red[16][68];
    __shared__ __align__(16) float srd[64];
    __shared__ __align__(16) float sld[64];
    __shared__ float ered[8];
    __shared__ int s_nz;

    int t = threadIdx.x;
    int rank = blockIdx.y * 64 + blockIdx.x;
    int v0 = blockIdx.x * 64;
    int b0 = blockIdx.y * 64;
    int tv = t & 15;       // v_local = tv + 16*vi
    int tb = t >> 4;       // b_local = tb + 16*bi

    // ---- phase 0: bow prefetch + denominator partial + scalars ----
    int cnt[4][4];
    #pragma unroll
    for (int bi = 0; bi < 4; ++bi)
        #pragma unroll
        for (int vi = 0; vi < 4; ++vi)
            cnt[bi][vi] = bow[(b0 + tb + 16 * bi) * Vc + v0 + tv + 16 * vi];

    if (t == 0) s_nz = 0;
    {
        int cq = t & 15, rr = t >> 4;
        int vp = rank * 16;
        float4 db = ((const float4*)beta)[(vp + rr) * 16 + cq];
        float4 de = ((const float4*)expn)[(vp + rr) * 16 + cq];
        __syncthreads();                       // s_nz init visible
        if (t < 128 && idxw[2 * t + 1] != 0u) atomicOr(&s_nz, 1);
        float4 a;
        a.x = db.x + de.x; a.y = db.y + de.y;
        a.z = db.z + de.z; a.w = db.w + de.w;
        *(float4*)&red[rr][cq * 4] = a;
        __syncthreads();
        if (t < 64) {
            float s = 0.f;
            #pragma unroll
            for (int r2 = 0; r2 < 16; ++r2) s += red[r2][t];
            atomicAdd(&g_denom[t], s);
        }
        if (rank == 255 && t == 0) {
            g_rho   = 1.f / powf((float)(iterp[0] + 5), 0.9f);
            g_ratio = (float)cmp[0] / (float)bcp[0];
            out[OUT_QZ] = 0.f;
        }
    }
    int stride = s_nz ? 1 : 2;    // int32 vs int64 batch_indices

    // ---- bar0 ARRIVE early (skew absorbed by the log-heavy fill below) ----
    unsigned ep0 = bar_arrive(0);

    // tile fill (NO denominator needed): ph=beta+expn, phL=ph*log(ph),
    // th_pre=traw, thL_pre=traw*log(traw)
    #pragma unroll
    for (int j = 0; j < 4; ++j) {
        int i = j * 256 + t;
        int r = i >> 4, cq = i & 15;
        float4 b4 = ((const float4*)beta)[(v0 + r) * 16 + cq];
        float4 e4 = ((const float4*)expn)[(v0 + r) * 16 + cq];
        float4 p;
        p.x = b4.x + e4.x; p.y = b4.y + e4.y;
        p.z = b4.z + e4.z; p.w = b4.w + e4.w;
        float4 pl;
        pl.x = p.x * __logf(p.x);
        pl.y = p.y * __logf(p.y);
        pl.z = p.z * __logf(p.z);
        pl.w = p.w * __logf(p.w);
        *(float4*)&ph [r][cq * 4] = p;
        *(float4*)&phL[r][cq * 4] = pl;
        int d = (int)idxw[(b0 + r) * stride];
        float4 al = ((const float4*)alpha)[cq];
        float4 pp = ((const float4*)pi   )[d * 16 + cq];
        float4 em = ((const float4*)expm )[d * 16 + cq];
        float4 traw, tl;
        traw.x = fmaf(al.x, pp.x, em.x);
        traw.y = fmaf(al.y, pp.y, em.y);
        traw.z = fmaf(al.z, pp.z, em.z);
        traw.w = fmaf(al.w, pp.w, em.w);
        tl.x = traw.x * __logf(traw.x);
        tl.y = traw.y * __logf(traw.y);
        tl.z = traw.z * __logf(traw.z);
        tl.w = traw.w * __logf(traw.w);
        *(float4*)&th [r][cq * 4] = traw;
        *(float4*)&thL[r][cq * 4] = tl;
    }

    // ---- bar0 WAIT (most blocks pass immediately) ----
    bar_wait(0, ep0);

    if (t < 64) {
        float d = g_denom[t];
        srd[t] = __fdividef(1.f, d);
        sld[t] = __logf(d);
    }
    __syncthreads();

    // scale theta tiles: th' = traw*rd ; thL' = (trawL - traw*ld)*rd
    #pragma unroll
    for (int j = 0; j < 4; ++j) {
        int i = j * 256 + t;
        int r = i >> 4, cq = i & 15;
        float4 tp  = *(const float4*)&th [r][cq * 4];
        float4 tlp = *(const float4*)&thL[r][cq * 4];
        float4 rd = *(const float4*)&srd[cq * 4];
        float4 ld = *(const float4*)&sld[cq * 4];
        float4 tt, tl;
        tt.x = tp.x * rd.x; tt.y = tp.y * rd.y;
        tt.z = tp.z * rd.z; tt.w = tp.w * rd.w;
        tl.x = (tlp.x - tp.x * ld.x) * rd.x;
        tl.y = (tlp.y - tp.y * ld.y) * rd.y;
        tl.z = (tlp.z - tp.z * ld.z) * rd.z;
        tl.w = (tlp.w - tp.w * ld.w) * rd.w;
        *(float4*)&th [r][cq * 4] = tt;
        *(float4*)&thL[r][cq * 4] = tl;
        if (blockIdx.x == 0)
            ((float4*)g_theta)[(b0 + r) * 16 + cq] = tt;
    }
    __syncthreads();

    // ---- phase 1: S/A GEMM ----
    unsigned long long S2[4][4], A2[4][4];
    #pragma unroll
    for (int bi = 0; bi < 4; ++bi)
        #pragma unroll
        for (int vi = 0; vi < 4; ++vi) { S2[bi][vi] = 0ull; A2[bi][vi] = 0ull; }

    #pragma unroll 4
    for (int kq = 0; kq < 16; ++kq) {
        ulonglong2 P[4], Q[4];
        #pragma unroll
        for (int vi = 0; vi < 4; ++vi) {
            P[vi] = *(const ulonglong2*)&ph [tv + 16 * vi][kq * 4];
            Q[vi] = *(const ulonglong2*)&phL[tv + 16 * vi][kq * 4];
        }
        #pragma unroll
        for (int bi = 0; bi < 4; ++bi) {
            ulonglong2 T = *(const ulonglong2*)&th [tb + 16 * bi][kq * 4];
            ulonglong2 L = *(const ulonglong2*)&thL[tb + 16 * bi][kq * 4];
            #pragma unroll
            for (int vi = 0; vi < 4; ++vi) {
                pfma(S2[bi][vi], T.x, P[vi].x);
                pfma(S2[bi][vi], T.y, P[vi].y);
                pfma(A2[bi][vi], L.x, P[vi].x);
                pfma(A2[bi][vi], L.y, P[vi].y);
                pfma(A2[bi][vi], T.x, Q[vi].x);
                pfma(A2[bi][vi], T.y, Q[vi].y);
            }
        }
    }

    // w, entropy
    float wv[4][4];
    float ent = 0.f;
    #pragma unroll
    for (int bi = 0; bi < 4; ++bi) {
        #pragma unroll
        for (int vi = 0; vi < 4; ++vi) {
            float S = psum(S2[bi][vi]);
            float A = psum(A2[bi][vi]);
            float sp = S + MINIf;
            float r  = __fdividef(1.f, sp);
            int c = cnt[bi][vi];
            wv[bi][vi] = (float)c * r;
            if (c > 0)
                ent += (A - S * __logf(sp)) * r;
        }
    }

    #pragma unroll
    for (int o = 16; o; o >>= 1)
        ent += __shfl_xor_sync(0xFFFFFFFFu, ent, o);
    if ((t & 31) == 0) ered[t >> 5] = ent;

    __syncthreads();
    if (t == 0) {
        float s = 0.f;
        #pragma unroll
        for (int w = 0; w < 8; ++w) s += ered[w];
        atomicAdd(&out[OUT_QZ], s);
    }

    // stage W into smem (overwrites thL)
    #pragma unroll
    for (int bi = 0; bi < 4; ++bi)
        #pragma unroll
        for (int vi = 0; vi < 4; ++vi)
            Wt[tb + 16 * bi][tv + 16 * vi] = wv[bi][vi];
    __syncthreads();

    // ---- phase 2 ----
    int kq2 = t & 15;
    int tr  = t >> 4;

    // 2a: Macc[b, k] += sum_c Wt[b_local][c] * ph[c][k]
    // W loads vectorized over c-quads (LDS.128 instead of 4 scalars).
    {
        unsigned long long acc[4][2];
        #pragma unroll
        for (int j = 0; j < 4; ++j) { acc[j][0] = 0ull; acc[j][1] = 0ull; }
        #pragma unroll 4
        for (int c4 = 0; c4 < 16; ++c4) {
            float Wc[4][4];
            #pragma unroll
            for (int j = 0; j < 4; ++j) {
                float4 w4 = *(const float4*)&Wt[tr + 16 * j][c4 * 4];
                Wc[j][0] = w4.x; Wc[j][1] = w4.y;
                Wc[j][2] = w4.z; Wc[j][3] = w4.w;
            }
            #pragma unroll
            for (int cc = 0; cc < 4; ++cc) {
                ulonglong2 p2 = *(const ulonglong2*)&ph[c4 * 4 + cc][kq2 * 4];
                #pragma unroll
                for (int j = 0; j < 4; ++j) {
                    unsigned long long w2 = fpack2(Wc[j][cc], Wc[j][cc]);
                    pfma(acc[j][0], w2, p2.x);
                    pfma(acc[j][1], w2, p2.y);
                }
            }
        }
        #pragma unroll
        for (int j = 0; j < 4; ++j) {
            float4 o4;
            punpack(acc[j][0], o4.x, o4.y);
            punpack(acc[j][1], o4.z, o4.w);
            atomicAdd((float4*)&g_Macc[(b0 + tr + 16 * j) * Kc + kq2 * 4], o4);
        }
    }

    // 2b: Nacc[v, k] += sum_c Wt[c][v_local] * th[c][k]
    // Thread's v-rows relabeled to tr*4+j so Wt[c][tr*4] is one LDS.128.
    {
        unsigned long long acc[4][2];
        #pragma unroll
        for (int j = 0; j < 4; ++j) { acc[j][0] = 0ull; acc[j][1] = 0ull; }
        #pragma unroll 8
        for (int c = 0; c < 64; ++c) {
            ulonglong2 t2 = *(const ulonglong2*)&th[c][kq2 * 4];
            float4 w4 = *(const float4*)&Wt[c][tr * 4];
            unsigned long long w20 = fpack2(w4.x, w4.x);
            unsigned long long w21 = fpack2(w4.y, w4.y);
            unsigned long long w22 = fpack2(w4.z, w4.z);
            unsigned long long w23 = fpack2(w4.w, w4.w);
            pfma(acc[0][0], w20, t2.x); pfma(acc[0][1], w20, t2.y);
            pfma(acc[1][0], w21, t2.x); pfma(acc[1][1], w21, t2.y);
            pfma(acc[2][0], w22, t2.x); pfma(acc[2][1], w22, t2.y);
            pfma(acc[3][0], w23, t2.x); pfma(acc[3][1], w23, t2.y);
        }
        #pragma unroll
        for (int j = 0; j < 4; ++j) {
            float4 o4;
            punpack(acc[j][0], o4.x, o4.y);
            punpack(acc[j][1], o4.z, o4.w);
            atomicAdd((float4*)&g_Nacc[(v0 + tr * 4 + j) * Kc + kq2 * 4], o4);
        }
    }

    // ---- bar1 ARRIVE; prefetch pure-input epilogue loads during skew ----
    unsigned ep1 = bar_arrive(1);

    int gid = rank * 256 + t;                 // 0..65535 == VK/4
    float4 pb = ((const float4*)beta)[gid];   // inputs: safe pre-wait
    float4 pe = ((const float4*)expn)[gid];
    float4 pem = make_float4(0.f, 0.f, 0.f, 0.f);
    if (gid < BK / 4) {
        int d = (int)idxw[((gid * 4) >> 6) * stride];
        pem = ((const float4*)expm)[d * 16 + (gid & 15)];
    }

    bar_wait(1, ep1);

    // ---- epilogue (L2-hot), accumulators read + self-reset ----
    float rho = g_rho, omr = 1.f - rho, rr2 = rho * g_ratio;
    const float4 z4 = make_float4(0.f, 0.f, 0.f, 0.f);

    {
        float4 n4 = ((const float4*)g_Nacc)[gid];
        float4 tn;
        tn.x = (pb.x + pe.x) * n4.x; tn.y = (pb.y + pe.y) * n4.y;
        tn.z = (pb.z + pe.z) * n4.z; tn.w = (pb.w + pe.w) * n4.w;
        ((float4*)g_Nacc)[gid] = z4;           // self-reset for next replay
        ((float4*)(out + OUT_TN))[gid] = tn;
        int c0 = OUT_NN + gid * 4;
        out[c0+0] = fmaf(omr, pe.x, rr2*tn.x);
        out[c0+1] = fmaf(omr, pe.y, rr2*tn.y);
        out[c0+2] = fmaf(omr, pe.z, rr2*tn.z);
        out[c0+3] = fmaf(omr, pe.w, rr2*tn.w);
    }

    if (gid < BK / 4) {                        // 4096 float4 units for TM/NM
        float4 t4 = ((const float4*)g_theta)[gid];
        float4 m4 = ((const float4*)g_Macc)[gid];
        float4 tm = make_float4(t4.x*m4.x, t4.y*m4.y, t4.z*m4.z, t4.w*m4.w);
        ((float4*)g_Macc)[gid] = z4;           // self-reset
        ((float4*)(out + OUT_TM))[gid] = tm;
        int c0 = OUT_NM + gid * 4;
        out[c0+0] = fmaf(omr, pem.x, rho*tm.x);
        out[c0+1] = fmaf(omr, pem.y, rho*tm.y);
        out[c0+2] = fmaf(omr, pem.z, rho*tm.z);
        out[c0+3] = fmaf(omr, pem.w, rho*tm.w);
    }

    if (rank == 0 && t < 64)
        g_denom[t] = 0.f;                      // self-reset
}

// ---------------------------------------------------------------------------
extern "C" void kernel_launch(void* const* d_in, const int* in_sizes, int n_in,
                              void* d_out, int out_size) {
    const int*          bow   = (const int*)d_in[0];
    const unsigned int* idxw  = (const unsigned int*)d_in[1];
    const float*        alpha = (const float*)d_in[2];
    const float*        pi    = (const float*)d_in[3];
    const float*        expm  = (const float*)d_in[4];
    const float*        beta  = (const float*)d_in[5];
    const float*        expn  = (const float*)d_in[6];
    const int*          iterp = (const int*)d_in[7];
    const int*          cmp   = (const int*)d_in[8];
    const int*          bcp   = (const int*)d_in[9];
    float* out = (float*)d_out;

    static int smem_set = 0;
    const int k_smem = 256 * 68 * 4;  // 69632 bytes dynamic
    if (!smem_set) {
        cudaFuncSetAttribute(mono, cudaFuncAttributeMaxDynamicSharedMemorySize, k_smem);
        smem_set = 1;
    }

    dim3 g(Vc / 64, Bc / 64);   // (64,4) = 256 blocks, all co-resident (2/SM)
    mono<<<g, 256, k_smem>>>(bow, idxw, alpha, pi, expm, beta, expn,
                             iterp, cmp, bcp, out);
}